// round 12
// baseline (speedup 1.0000x reference)
#include <cuda_runtime.h>

#define IMW 1024
#define IMH 1024
#define HW  (IMW * IMH)
#define TW 16
#define TH 64
#define HALO_W 22
#define HALO_H 70
#define SSTRIDE 24
#define CH_STRIDE (HALO_H * SSTRIDE)    // 1680 floats per channel
#define F_WORDS (11 * CH_STRIDE)        // 18480 floats = 73,920 B
#define EPSR 1e-4f
#define SGN2 0x8000000080000000ULL

typedef unsigned long long ull;

// ---- packed f32x2 helpers -------------------------------------------------
__device__ __forceinline__ ull pk2(float lo, float hi) {
    ull r;
    asm("mov.b64 %0, {%1, %2};" : "=l"(r) : "f"(lo), "f"(hi));
    return r;
}
__device__ __forceinline__ void ffma2(ull& d, ull a, ull b) {
    asm("fma.rn.f32x2 %0, %1, %2, %0;" : "+l"(d) : "l"(a), "l"(b));
}
__device__ __forceinline__ float upk(ull v, int hi) {
    float lo, h;
    asm("mov.b64 {%0, %1}, %2;" : "=f"(lo), "=f"(h) : "l"(v));
    return hi ? h : lo;
}

// 7 horizontal taps at one row-pair base; SUB subtracts (sign-flip 1st operand)
template<bool SUB>
__device__ __forceinline__ void tap7(const float* __restrict__ rp,
                                     ull ata[36], ull aty[24]) {
#pragma unroll
    for (int dx = 0; dx < 7; ++dx) {
        ull v[11];
#pragma unroll
        for (int ch = 0; ch < 11; ++ch)
            v[ch] = pk2(rp[ch * CH_STRIDE + dx],
                        rp[ch * CH_STRIDE + dx + SSTRIDE]);
        int k = 0;
#pragma unroll
        for (int i = 0; i < 8; ++i) {
            const ull si = SUB ? (v[i] ^ SGN2) : v[i];
#pragma unroll
            for (int j = i; j < 8; ++j) { ffma2(ata[k], si, v[j]); ++k; }
#pragma unroll
            for (int c = 0; c < 3; ++c) ffma2(aty[i * 3 + c], si, v[8 + c]);
        }
    }
}

// R1's scalar per-pixel solve, run with packed accumulators still live.
__device__ __forceinline__ void solve2(const ull ata[36], const ull aty[24],
                                       const float* __restrict__ S,
                                       int lp, int lx, int gy, int gx,
                                       float* __restrict__ out) {
#pragma unroll 1
    for (int p = 0; p < 2; ++p) {
        float A[8][9];
        {
            int k = 0;
#pragma unroll
            for (int i = 0; i < 8; ++i)
#pragma unroll
                for (int j = i; j < 8; ++j) {
                    const float vv = upk(ata[k], p); ++k;
                    A[i][j] = vv;
                    A[j][i] = vv;
                }
        }
#pragma unroll
        for (int i = 0; i < 8; ++i) A[i][i] += EPSR;

        // RHS: center-pixel features (local row lp+3+p, col lx+3)
        const float* cp = &S[(lp + 3 + p) * SSTRIDE + (lx + 3)];
#pragma unroll
        for (int i = 0; i < 8; ++i) A[i][8] = cp[i * CH_STRIDE];

        // Gaussian elimination (no pivoting; SPD + Tikhonov)
#pragma unroll
        for (int kk = 0; kk < 8; ++kk) {
            const float inv = 1.0f / A[kk][kk];
#pragma unroll
            for (int j = 0; j < 9; ++j)
                if (j > kk) A[kk][j] *= inv;
#pragma unroll
            for (int r = 0; r < 8; ++r)
                if (r > kk) {
                    const float m = A[r][kk];
#pragma unroll
                    for (int j = 0; j < 9; ++j)
                        if (j > kk) A[r][j] = fmaf(-m, A[kk][j], A[r][j]);
                }
        }
        float x[8];
#pragma unroll
        for (int i = 7; i >= 0; --i) {
            float s = A[i][8];
#pragma unroll
            for (int j = 0; j < 8; ++j)
                if (j > i) s = fmaf(-A[i][j], x[j], s);
            x[i] = s;
        }

#pragma unroll
        for (int c = 0; c < 3; ++c) {
            float o = 0.0f;
#pragma unroll
            for (int i = 0; i < 8; ++i)
                o = fmaf(x[i], upk(aty[i * 3 + c], p), o);
            out[c * HW + (gy + p) * IMW + gx] = o;
        }
    }
}

__global__ __launch_bounds__(128)
void ls_kernel(const float* __restrict__ inp,
               const float* __restrict__ dep,
               const float* __restrict__ alb,
               const float* __restrict__ nrm,
               float* __restrict__ out)
{
    extern __shared__ float S[];            // S[ch][r][c], stride 24

    const int tid = threadIdx.x;
    const int bx = blockIdx.x, by = blockIdx.y;
    const int gx0 = bx * TW - 3;
    const int gy0 = by * TH - 3;

    // ---- stage halo features (zeros outside image) ----
    for (int idx = tid; idx < HALO_H * HALO_W; idx += 128) {
        const int r = idx / HALO_W;
        const int c = idx - r * HALO_W;
        const int gy = gy0 + r;
        const int gx = gx0 + c;
        float v[11];
        if ((unsigned)gy < (unsigned)IMH && (unsigned)gx < (unsigned)IMW) {
            const int g = gy * IMW + gx;
            v[0] = 1.0f;
            v[1] = dep[g];
            v[2] = alb[g];  v[3] = alb[g + HW];  v[4] = alb[g + 2 * HW];
            v[5] = nrm[g];  v[6] = nrm[g + HW];  v[7] = nrm[g + 2 * HW];
            v[8] = inp[g];  v[9] = inp[g + HW];  v[10] = inp[g + 2 * HW];
        } else {
#pragma unroll
            for (int ch = 0; ch < 11; ++ch) v[ch] = 0.0f;
        }
#pragma unroll
        for (int ch = 0; ch < 11; ++ch)
            S[ch * CH_STRIDE + r * SSTRIDE + c] = v[ch];
    }
    __syncthreads();

    const int lx = tid & 15;
    const int ty = tid >> 4;                // 0..7
    const int lp0 = 8 * ty;                 // pairs at lp0, lp0+2, lp0+4, lp0+6
    const int gx = bx * TW + lx;

    ull ata[36];
    ull aty[24];
#pragma unroll
    for (int m = 0; m < 36; ++m) ata[m] = 0ULL;
#pragma unroll
    for (int m = 0; m < 24; ++m) aty[m] = 0ULL;

    // ---- pair 0: full 49 taps ----
    {
        const float* b = &S[lp0 * SSTRIDE + lx];
#pragma unroll
        for (int dy = 0; dy < 7; ++dy)
            tap7<false>(b + dy * SSTRIDE, ata, aty);
    }
    solve2(ata, aty, S, lp0, lx, by * TH + lp0, gx, out);

    // ---- pairs 1..3: slide by 2 rows each ----
#pragma unroll
    for (int k = 1; k < 4; ++k) {
        const int lp = lp0 + 2 * k;
        const float* b = &S[lp * SSTRIDE + lx];
        tap7<false>(b + 5 * SSTRIDE, ata, aty);
        tap7<false>(b + 6 * SSTRIDE, ata, aty);
        tap7<true >(b - 2 * SSTRIDE, ata, aty);
        tap7<true >(b - 1 * SSTRIDE, ata, aty);
        solve2(ata, aty, S, lp, lx, by * TH + lp, gx, out);
    }
}

extern "C" void kernel_launch(void* const* d_in, const int* in_sizes, int n_in,
                              void* d_out, int out_size) {
    const float* inp   = (const float*)d_in[0];
    const float* depth = (const float*)d_in[1];
    const float* alb   = (const float*)d_in[2];
    const float* nrm   = (const float*)d_in[3];
    float* out = (float*)d_out;

    cudaFuncSetAttribute(ls_kernel, cudaFuncAttributeMaxDynamicSharedMemorySize,
                         F_WORDS * 4);
    dim3 grid(IMW / TW, IMH / TH);   // (64, 16) = 1024 CTAs
    ls_kernel<<<grid, 128, F_WORDS * 4>>>(inp, depth, alb, nrm, out);
}

// round 13
// speedup vs baseline: 3.1008x; 3.1008x over previous
#include <cuda_runtime.h>

#define IMW 1024
#define IMH 1024
#define HW  (IMW * IMH)
#define TW 16
#define TH 32
#define HALO_W 22
#define HALO_H 38
#define SSTRIDE 24
#define CH_STRIDE (HALO_H * SSTRIDE)    // 912 floats per channel
#define F_WORDS (11 * CH_STRIDE)        // 10032 floats = 40,128 B
#define XSTR 61                          // slot stride in ull
#define X_ULL (128 * XSTR)               // 7808 ull = 62,464 B
#define SMEM_BYTES (F_WORDS * 4 + X_ULL * 8)   // 102,592 B -> 2 CTAs/SM
#define EPSR 1e-4f
#define SGN2 0x8000000080000000ULL

typedef unsigned long long ull;

// ---- packed f32x2 helpers -------------------------------------------------
__device__ __forceinline__ ull pk2(float lo, float hi) {
    ull r;
    asm("mov.b64 %0, {%1, %2};" : "=l"(r) : "f"(lo), "f"(hi));
    return r;
}
__device__ __forceinline__ void ffma2(ull& d, ull a, ull b) {
    asm("fma.rn.f32x2 %0, %1, %2, %0;" : "+l"(d) : "l"(a), "l"(b));
}
__device__ __forceinline__ float upk(ull v, int hi) {
    float lo, h;
    asm("mov.b64 {%0, %1}, %2;" : "=f"(lo), "=f"(h) : "l"(v));
    return hi ? h : lo;
}

// 7 horizontal taps at one row-pair base; SUB subtracts (sign-flip 1st operand)
template<bool SUB>
__device__ __forceinline__ void tap7(const float* __restrict__ rp,
                                     ull ata[36], ull aty[24]) {
#pragma unroll
    for (int dx = 0; dx < 7; ++dx) {
        ull v[11];
#pragma unroll
        for (int ch = 0; ch < 11; ++ch)
            v[ch] = pk2(rp[ch * CH_STRIDE + dx],
                        rp[ch * CH_STRIDE + dx + SSTRIDE]);
        int k = 0;
#pragma unroll
        for (int i = 0; i < 8; ++i) {
            const ull si = SUB ? (v[i] ^ SGN2) : v[i];
#pragma unroll
            for (int j = i; j < 8; ++j) { ffma2(ata[k], si, v[j]); ++k; }
#pragma unroll
            for (int c = 0; c < 3; ++c) ffma2(aty[i * 3 + c], si, v[8 + c]);
        }
    }
}

// R1's scalar per-pixel solve, consuming packed accumulators (their LAST use).
__device__ __forceinline__ void solve_reg(const ull ata[36], const ull aty[24],
                                          const float* __restrict__ S,
                                          int lp, int lx, int gy, int gx,
                                          float* __restrict__ out) {
#pragma unroll 1
    for (int p = 0; p < 2; ++p) {
        float A[8][9];
        {
            int k = 0;
#pragma unroll
            for (int i = 0; i < 8; ++i)
#pragma unroll
                for (int j = i; j < 8; ++j) {
                    const float vv = upk(ata[k], p); ++k;
                    A[i][j] = vv;
                    A[j][i] = vv;
                }
        }
#pragma unroll
        for (int i = 0; i < 8; ++i) A[i][i] += EPSR;

        const float* cp = &S[(lp + 3 + p) * SSTRIDE + (lx + 3)];
#pragma unroll
        for (int i = 0; i < 8; ++i) A[i][8] = cp[i * CH_STRIDE];

#pragma unroll
        for (int kk = 0; kk < 8; ++kk) {
            const float inv = 1.0f / A[kk][kk];
#pragma unroll
            for (int j = 0; j < 9; ++j)
                if (j > kk) A[kk][j] *= inv;
#pragma unroll
            for (int r = 0; r < 8; ++r)
                if (r > kk) {
                    const float m = A[r][kk];
#pragma unroll
                    for (int j = 0; j < 9; ++j)
                        if (j > kk) A[r][j] = fmaf(-m, A[kk][j], A[r][j]);
                }
        }
        float x[8];
#pragma unroll
        for (int i = 7; i >= 0; --i) {
            float s = A[i][8];
#pragma unroll
            for (int j = 0; j < 8; ++j)
                if (j > i) s = fmaf(-A[i][j], x[j], s);
            x[i] = s;
        }

#pragma unroll
        for (int c = 0; c < 3; ++c) {
            float o = 0.0f;
#pragma unroll
            for (int i = 0; i < 8; ++i)
                o = fmaf(x[i], upk(aty[i * 3 + c], p), o);
            out[c * HW + (gy + p) * IMW + gx] = o;
        }
    }
}

// Same scalar solve, but moments sourced from the thread's smem slot
// (slotf[2*m + p]: m=0..35 AtA tri, m=36..59 AtY). No big register arrays live.
__device__ __forceinline__ void solve_mem(const float* __restrict__ slotf,
                                          const float* __restrict__ S,
                                          int lp, int lx, int gy, int gx,
                                          float* __restrict__ out) {
#pragma unroll 1
    for (int p = 0; p < 2; ++p) {
        float A[8][9];
        {
            int k = 0;
#pragma unroll
            for (int i = 0; i < 8; ++i)
#pragma unroll
                for (int j = i; j < 8; ++j) {
                    const float vv = slotf[2 * k + p]; ++k;
                    A[i][j] = vv;
                    A[j][i] = vv;
                }
        }
#pragma unroll
        for (int i = 0; i < 8; ++i) A[i][i] += EPSR;

        const float* cp = &S[(lp + 3 + p) * SSTRIDE + (lx + 3)];
#pragma unroll
        for (int i = 0; i < 8; ++i) A[i][8] = cp[i * CH_STRIDE];

#pragma unroll
        for (int kk = 0; kk < 8; ++kk) {
            const float inv = 1.0f / A[kk][kk];
#pragma unroll
            for (int j = 0; j < 9; ++j)
                if (j > kk) A[kk][j] *= inv;
#pragma unroll
            for (int r = 0; r < 8; ++r)
                if (r > kk) {
                    const float m = A[r][kk];
#pragma unroll
                    for (int j = 0; j < 9; ++j)
                        if (j > kk) A[r][j] = fmaf(-m, A[kk][j], A[r][j]);
                }
        }
        float x[8];
#pragma unroll
        for (int i = 7; i >= 0; --i) {
            float s = A[i][8];
#pragma unroll
            for (int j = 0; j < 8; ++j)
                if (j > i) s = fmaf(-A[i][j], x[j], s);
            x[i] = s;
        }

#pragma unroll
        for (int c = 0; c < 3; ++c) {
            float o = 0.0f;
#pragma unroll
            for (int i = 0; i < 8; ++i)
                o = fmaf(x[i], slotf[2 * (36 + i * 3 + c) + p], o);
            out[c * HW + (gy + p) * IMW + gx] = o;
        }
    }
}

__global__ __launch_bounds__(128)
void ls_kernel(const float* __restrict__ inp,
               const float* __restrict__ dep,
               const float* __restrict__ alb,
               const float* __restrict__ nrm,
               float* __restrict__ out)
{
    extern __shared__ float SM[];
    float* S = SM;                          // S[ch][r][c], stride 24
    ull* X = (ull*)(SM + F_WORDS);          // slots: 128 x 61 ull

    const int tid = threadIdx.x;
    const int bx = blockIdx.x, by = blockIdx.y;
    const int gx0 = bx * TW - 3;
    const int gy0 = by * TH - 3;

    // ---- stage halo features (zeros outside image) ----
    for (int idx = tid; idx < HALO_H * HALO_W; idx += 128) {
        const int r = idx / HALO_W;
        const int c = idx - r * HALO_W;
        const int gy = gy0 + r;
        const int gx = gx0 + c;
        float v[11];
        if ((unsigned)gy < (unsigned)IMH && (unsigned)gx < (unsigned)IMW) {
            const int g = gy * IMW + gx;
            v[0] = 1.0f;
            v[1] = dep[g];
            v[2] = alb[g];  v[3] = alb[g + HW];  v[4] = alb[g + 2 * HW];
            v[5] = nrm[g];  v[6] = nrm[g + HW];  v[7] = nrm[g + 2 * HW];
            v[8] = inp[g];  v[9] = inp[g + HW];  v[10] = inp[g + 2 * HW];
        } else {
#pragma unroll
            for (int ch = 0; ch < 11; ++ch) v[ch] = 0.0f;
        }
#pragma unroll
        for (int ch = 0; ch < 11; ++ch)
            S[ch * CH_STRIDE + r * SSTRIDE + c] = v[ch];
    }
    __syncthreads();

    const int lx = tid & 15;
    const int ty = tid >> 4;                // 0..7
    const int lp0 = 4 * ty;                 // pairs at lp0 and lp0+2
    const int gx = bx * TW + lx;
    ull* xp = X + tid * XSTR;

    ull ata[36];
    ull aty[24];
#pragma unroll
    for (int m = 0; m < 36; ++m) ata[m] = 0ULL;
#pragma unroll
    for (int m = 0; m < 24; ++m) aty[m] = 0ULL;

    // ---- pair 0: full 49 taps ----
    {
        const float* b = &S[lp0 * SSTRIDE + lx];
#pragma unroll
        for (int dy = 0; dy < 7; ++dy)
            tap7<false>(b + dy * SSTRIDE, ata, aty);
    }

    // ---- stash pair 0's moments (reads A; lifetime continues) ----
#pragma unroll
    for (int m = 0; m < 36; ++m) xp[m] = ata[m];
#pragma unroll
    for (int m = 0; m < 24; ++m) xp[36 + m] = aty[m];

    // ---- slide 2 rows to pair 1 ----
    {
        const int lp = lp0 + 2;
        const float* b = &S[lp * SSTRIDE + lx];
        tap7<false>(b + 5 * SSTRIDE, ata, aty);
        tap7<false>(b + 6 * SSTRIDE, ata, aty);
        tap7<true >(b - 2 * SSTRIDE, ata, aty);
        tap7<true >(b - 1 * SSTRIDE, ata, aty);

        // solve pair 1: A's LAST use — dies into the solve (R1 pattern)
        solve_reg(ata, aty, S, lp, lx, by * TH + lp, gx, out);
    }

    // ---- solve pair 0 from the smem slot (A long dead) ----
    solve_mem((const float*)xp, S, lp0, lx, by * TH + lp0, gx, out);
}

extern "C" void kernel_launch(void* const* d_in, const int* in_sizes, int n_in,
                              void* d_out, int out_size) {
    const float* inp   = (const float*)d_in[0];
    const float* depth = (const float*)d_in[1];
    const float* alb   = (const float*)d_in[2];
    const float* nrm   = (const float*)d_in[3];
    float* out = (float*)d_out;

    cudaFuncSetAttribute(ls_kernel, cudaFuncAttributeMaxDynamicSharedMemorySize,
                         SMEM_BYTES);
    dim3 grid(IMW / TW, IMH / TH);   // (64, 32) = 2048 CTAs
    ls_kernel<<<grid, 128, SMEM_BYTES>>>(inp, depth, alb, nrm, out);
}

// round 14
// speedup vs baseline: 4.7718x; 1.5389x over previous
#include <cuda_runtime.h>

#define IMW 1024
#define IMH 1024
#define HW  (IMW * IMH)
#define TILE_W 16
#define TILE_H 32
#define HALO_W (TILE_W + 6)   // 22
#define HALO_H (TILE_H + 6)   // 38
#define SSTRIDE 24            // padded row stride (floats)
#define CH_STRIDE (HALO_H * SSTRIDE)  // 912 floats per channel
#define EPSR 1e-4f

typedef unsigned long long ull;

// ---- packed f32x2 helpers -------------------------------------------------
__device__ __forceinline__ ull pk2(float lo, float hi) {
    ull r;
    asm("mov.b64 %0, {%1, %2};" : "=l"(r) : "f"(lo), "f"(hi));
    return r;
}
__device__ __forceinline__ void ffma2(ull& d, ull a, ull b) {
    asm("fma.rn.f32x2 %0, %1, %2, %0;" : "+l"(d) : "l"(a), "l"(b));
}
__device__ __forceinline__ float upk(ull v, int hi) {
    float lo, h;
    asm("mov.b64 {%0, %1}, %2;" : "=f"(lo), "=f"(h) : "l"(v));
    return hi ? h : lo;
}

__global__ __launch_bounds__(256)
void ls_kernel(const float* __restrict__ inp,
               const float* __restrict__ depth,
               const float* __restrict__ alb,
               const float* __restrict__ nrm,
               float* __restrict__ out)
{
    // 11 channels: [valid(=1), depth, albedo x3, normal x3, input x3]
    __shared__ float S[11 * CH_STRIDE];

    const int tid = threadIdx.x;
    const int bx = blockIdx.x, by = blockIdx.y;
    const int gx0 = bx * TILE_W - 3;
    const int gy0 = by * TILE_H - 3;

    // ---- stage halo tile into smem (zeros outside the image) ----
    for (int idx = tid; idx < HALO_H * HALO_W; idx += 256) {
        const int r = idx / HALO_W;
        const int c = idx - r * HALO_W;
        const int gy = gy0 + r;
        const int gx = gx0 + c;
        float v[11];
        if ((unsigned)gy < (unsigned)IMH && (unsigned)gx < (unsigned)IMW) {
            const int g = gy * IMW + gx;
            v[0] = 1.0f;
            v[1] = depth[g];
            v[2] = alb[g];          v[3] = alb[g + HW];   v[4] = alb[g + 2 * HW];
            v[5] = nrm[g];          v[6] = nrm[g + HW];   v[7] = nrm[g + 2 * HW];
            v[8] = inp[g];          v[9] = inp[g + HW];   v[10] = inp[g + 2 * HW];
        } else {
#pragma unroll
            for (int ch = 0; ch < 11; ++ch) v[ch] = 0.0f;
        }
#pragma unroll
        for (int ch = 0; ch < 11; ++ch)
            S[ch * CH_STRIDE + r * SSTRIDE + c] = v[ch];
    }
    __syncthreads();

    // ---- per-thread: two vertically adjacent pixels, packed f32x2 ----
    const int lx = tid & 15;
    const int ly0 = (tid >> 4) * 2;

    ull ata[36];  // upper triangle i<=j of 8x8
    ull aty[24];  // i*3 + c
#pragma unroll
    for (int i = 0; i < 36; ++i) ata[i] = 0ULL;
#pragma unroll
    for (int i = 0; i < 24; ++i) aty[i] = 0ULL;

    // dx-outer / dy-inner with row register reuse: per column load each of the
    // 8 distinct window rows once (11 LDS each); taps use (rowpair) = (lo, hi).
    const float* base = &S[ly0 * SSTRIDE + lx];
#pragma unroll 1
    for (int dx = 0; dx < 7; ++dx) {
        const float* cp = base + dx;
        float fa[11], fb[11];
#pragma unroll
        for (int ch = 0; ch < 11; ++ch) fa[ch] = cp[ch * CH_STRIDE];  // row ly0
#pragma unroll
        for (int dy = 0; dy < 7; ++dy) {
            float* lo = (dy & 1) ? fb : fa;     // row ly0+dy (loaded last iter)
            float* hi = (dy & 1) ? fa : fb;     // row ly0+dy+1 (fresh)
            const float* rp = cp + (dy + 1) * SSTRIDE;
#pragma unroll
            for (int ch = 0; ch < 11; ++ch) hi[ch] = rp[ch * CH_STRIDE];

            ull v[11];
#pragma unroll
            for (int ch = 0; ch < 11; ++ch) v[ch] = pk2(lo[ch], hi[ch]);
            int k = 0;
#pragma unroll
            for (int i = 0; i < 8; ++i)
#pragma unroll
                for (int j = i; j < 8; ++j) { ffma2(ata[k], v[i], v[j]); ++k; }
#pragma unroll
            for (int i = 0; i < 8; ++i)
#pragma unroll
                for (int c = 0; c < 3; ++c) ffma2(aty[i * 3 + c], v[i], v[8 + c]);
        }
    }

    // ---- per-pixel solve:  x = (AtA + eps I)^{-1} f_center ;  out_c = x . AtY_c
#pragma unroll 1
    for (int p = 0; p < 2; ++p) {
        float A[8][9];
        {
            int k = 0;
#pragma unroll
            for (int i = 0; i < 8; ++i)
#pragma unroll
                for (int j = i; j < 8; ++j) {
                    const float vv = upk(ata[k], p); ++k;
                    A[i][j] = vv;
                    A[j][i] = vv;
                }
        }
#pragma unroll
        for (int i = 0; i < 8; ++i) A[i][i] += EPSR;

        // RHS: center-pixel features
        const float* cp = &S[(ly0 + 3 + p) * SSTRIDE + (lx + 3)];
#pragma unroll
        for (int i = 0; i < 8; ++i) A[i][8] = cp[i * CH_STRIDE];

        // Gaussian elimination (no pivoting; SPD + Tikhonov)
#pragma unroll
        for (int kk = 0; kk < 8; ++kk) {
            const float inv = 1.0f / A[kk][kk];
#pragma unroll
            for (int j = 0; j < 9; ++j)
                if (j > kk) A[kk][j] *= inv;
#pragma unroll
            for (int r = 0; r < 8; ++r)
                if (r > kk) {
                    const float m = A[r][kk];
#pragma unroll
                    for (int j = 0; j < 9; ++j)
                        if (j > kk) A[r][j] = fmaf(-m, A[kk][j], A[r][j]);
                }
        }
        float x[8];
#pragma unroll
        for (int i = 7; i >= 0; --i) {
            float s = A[i][8];
#pragma unroll
            for (int j = 0; j < 8; ++j)
                if (j > i) s = fmaf(-A[i][j], x[j], s);
            x[i] = s;
        }

        const int gy = by * TILE_H + ly0 + p;
        const int gx = bx * TILE_W + lx;
#pragma unroll
        for (int c = 0; c < 3; ++c) {
            float o = 0.0f;
#pragma unroll
            for (int i = 0; i < 8; ++i)
                o = fmaf(x[i], upk(aty[i * 3 + c], p), o);
            out[c * HW + gy * IMW + gx] = o;
        }
    }
}

extern "C" void kernel_launch(void* const* d_in, const int* in_sizes, int n_in,
                              void* d_out, int out_size) {
    const float* inp   = (const float*)d_in[0];
    const float* depth = (const float*)d_in[1];
    const float* alb   = (const float*)d_in[2];
    const float* nrm   = (const float*)d_in[3];
    float* out = (float*)d_out;

    dim3 grid(IMW / TILE_W, IMH / TILE_H);
    ls_kernel<<<grid, 256>>>(inp, depth, alb, nrm, out);
}

// round 15
// speedup vs baseline: 6.7327x; 1.4109x over previous
#include <cuda_runtime.h>

#define IMW 1024
#define IMH 1024
#define HW  (IMW * IMH)
#define TILE_W 16
#define TILE_H 64
#define HALO_W 22
#define HALO_H 70
#define SSTRIDE 28            // 4*28 % 32 == 16 -> warp halves on disjoint banks
#define CH_STRIDE (HALO_H * SSTRIDE)   // 1960 floats per channel
#define F_WORDS (11 * CH_STRIDE)       // 21560 floats = 86,240 B
#define XSTR 61                         // slot stride (ull), conflict-free
#define X_ULL (256 * XSTR)              // 124,928 B
#define SMEM_BYTES (F_WORDS * 4 + X_ULL * 8)   // 211,168 B
#define EPSR 1e-4f
#define SGN2 0x8000000080000000ULL

typedef unsigned long long ull;

// ---- packed f32x2 helpers -------------------------------------------------
__device__ __forceinline__ ull pk2(float lo, float hi) {
    ull r;
    asm("mov.b64 %0, {%1, %2};" : "=l"(r) : "f"(lo), "f"(hi));
    return r;
}
__device__ __forceinline__ void ffma2(ull& d, ull a, ull b) {
    asm("fma.rn.f32x2 %0, %1, %2, %0;" : "+l"(d) : "l"(a), "l"(b));
}
__device__ __forceinline__ float upk(ull v, int hi) {
    float lo, h;
    asm("mov.b64 {%0, %1}, %2;" : "=f"(lo), "=f"(h) : "l"(v));
    return hi ? h : lo;
}

// one pair-row tap block of 7 horizontal taps; SUB flips sign of 1st operand
template<bool SUB>
__device__ __forceinline__ void tap7(const float* __restrict__ rp,
                                     ull ata[36], ull aty[24]) {
#pragma unroll
    for (int dx = 0; dx < 7; ++dx) {
        ull v[11];
#pragma unroll
        for (int ch = 0; ch < 11; ++ch)
            v[ch] = pk2(rp[ch * CH_STRIDE + dx],
                        rp[ch * CH_STRIDE + dx + SSTRIDE]);
        int k = 0;
#pragma unroll
        for (int i = 0; i < 8; ++i) {
            const ull si = SUB ? (v[i] ^ SGN2) : v[i];
#pragma unroll
            for (int j = i; j < 8; ++j) { ffma2(ata[k], si, v[j]); ++k; }
#pragma unroll
            for (int c = 0; c < 3; ++c) ffma2(aty[i * 3 + c], si, v[8 + c]);
        }
    }
}

// R1's scalar per-pixel solve; consumes ata/aty (their LAST use).
__device__ __forceinline__ void solve2(const ull ata[36], const ull aty[24],
                                       const float* __restrict__ S,
                                       int lp, int lx, int gy, int gx,
                                       float* __restrict__ out) {
#pragma unroll 1
    for (int p = 0; p < 2; ++p) {
        float A[8][9];
        {
            int k = 0;
#pragma unroll
            for (int i = 0; i < 8; ++i)
#pragma unroll
                for (int j = i; j < 8; ++j) {
                    const float vv = upk(ata[k], p); ++k;
                    A[i][j] = vv;
                    A[j][i] = vv;
                }
        }
#pragma unroll
        for (int i = 0; i < 8; ++i) A[i][i] += EPSR;

        const float* cp = &S[(lp + 3 + p) * SSTRIDE + (lx + 3)];
#pragma unroll
        for (int i = 0; i < 8; ++i) A[i][8] = cp[i * CH_STRIDE];

#pragma unroll
        for (int kk = 0; kk < 8; ++kk) {
            const float inv = 1.0f / A[kk][kk];
#pragma unroll
            for (int j = 0; j < 9; ++j)
                if (j > kk) A[kk][j] *= inv;
#pragma unroll
            for (int r = 0; r < 8; ++r)
                if (r > kk) {
                    const float m = A[r][kk];
#pragma unroll
                    for (int j = 0; j < 9; ++j)
                        if (j > kk) A[r][j] = fmaf(-m, A[kk][j], A[r][j]);
                }
        }
        float x[8];
#pragma unroll
        for (int i = 7; i >= 0; --i) {
            float s = A[i][8];
#pragma unroll
            for (int j = 0; j < 8; ++j)
                if (j > i) s = fmaf(-A[i][j], x[j], s);
            x[i] = s;
        }

#pragma unroll
        for (int c = 0; c < 3; ++c) {
            float o = 0.0f;
#pragma unroll
            for (int i = 0; i < 8; ++i)
                o = fmaf(x[i], upk(aty[i * 3 + c], p), o);
            out[c * HW + (gy + p) * IMW + gx] = o;
        }
    }
}

__global__ __launch_bounds__(256)
void ls_kernel(const float* __restrict__ inp,
               const float* __restrict__ depth,
               const float* __restrict__ alb,
               const float* __restrict__ nrm,
               float* __restrict__ out)
{
    extern __shared__ float SM[];
    float* S = SM;                          // S[ch][r][c], stride 28
    ull* X = (ull*)(SM + F_WORDS);          // 256 private slots x 61 ull

    const int tid = threadIdx.x;
    const int bx = blockIdx.x, by = blockIdx.y;
    const int gx0 = bx * TILE_W - 3;
    const int gy0 = by * TILE_H - 3;

    // ---- stage halo tile into smem (zeros outside the image) ----
    for (int idx = tid; idx < HALO_H * HALO_W; idx += 256) {
        const int r = idx / HALO_W;
        const int c = idx - r * HALO_W;
        const int gy = gy0 + r;
        const int gx = gx0 + c;
        float v[11];
        if ((unsigned)gy < (unsigned)IMH && (unsigned)gx < (unsigned)IMW) {
            const int g = gy * IMW + gx;
            v[0] = 1.0f;
            v[1] = depth[g];
            v[2] = alb[g];  v[3] = alb[g + HW];  v[4] = alb[g + 2 * HW];
            v[5] = nrm[g];  v[6] = nrm[g + HW];  v[7] = nrm[g + 2 * HW];
            v[8] = inp[g];  v[9] = inp[g + HW];  v[10] = inp[g + 2 * HW];
        } else {
#pragma unroll
            for (int ch = 0; ch < 11; ++ch) v[ch] = 0.0f;
        }
#pragma unroll
        for (int ch = 0; ch < 11; ++ch)
            S[ch * CH_STRIDE + r * SSTRIDE + c] = v[ch];
    }
    __syncthreads();

    const int lx = tid & 15;
    const int ty = tid >> 4;                // 0..15
    const int lp0 = 4 * ty;                 // pairs at lp0 and lp0+2
    const int gx = bx * TILE_W + lx;
    ull* xp = X + tid * XSTR;

    ull ata[36];
    ull aty[24];
#pragma unroll
    for (int i = 0; i < 36; ++i) ata[i] = 0ULL;
#pragma unroll
    for (int i = 0; i < 24; ++i) aty[i] = 0ULL;

    // ---- pair 0: full 49 taps (R1-verbatim loop shape) ----
    {
        const float* base = &S[lp0 * SSTRIDE + lx];
#pragma unroll 1
        for (int dy = 0; dy < 7; ++dy)
            tap7<false>(base + dy * SSTRIDE, ata, aty);
    }

    // ---- stash pair-0 moments (write-only; A still live) ----
#pragma unroll
    for (int m = 0; m < 36; ++m) xp[m] = ata[m];
#pragma unroll
    for (int m = 0; m < 24; ++m) xp[36 + m] = aty[m];

    // ---- solve pair 0: A dies into the solve (R1's proven pattern) ----
    solve2(ata, aty, S, lp0, lx, by * TILE_H + lp0, gx, out);

    // ---- lifetime fence: no shared load moves above this barrier ----
    __syncthreads();

    // ---- reload + slide 2 rows -> pair 1 ----
    {
        ull ata2[36];
        ull aty2[24];
#pragma unroll
        for (int m = 0; m < 36; ++m) ata2[m] = xp[m];
#pragma unroll
        for (int m = 0; m < 24; ++m) aty2[m] = xp[36 + m];

        const int lp = lp0 + 2;
        const float* b = &S[lp * SSTRIDE + lx];
        tap7<false>(b + 5 * SSTRIDE, ata2, aty2);
        tap7<false>(b + 6 * SSTRIDE, ata2, aty2);
        tap7<true >(b - 2 * SSTRIDE, ata2, aty2);
        tap7<true >(b - 1 * SSTRIDE, ata2, aty2);

        // solve pair 1: A' dies into the solve
        solve2(ata2, aty2, S, lp, lx, by * TILE_H + lp, gx, out);
    }
}

extern "C" void kernel_launch(void* const* d_in, const int* in_sizes, int n_in,
                              void* d_out, int out_size) {
    const float* inp   = (const float*)d_in[0];
    const float* depth = (const float*)d_in[1];
    const float* alb   = (const float*)d_in[2];
    const float* nrm   = (const float*)d_in[3];
    float* out = (float*)d_out;

    cudaFuncSetAttribute(ls_kernel, cudaFuncAttributeMaxDynamicSharedMemorySize,
                         SMEM_BYTES);
    dim3 grid(IMW / TILE_W, IMH / TILE_H);   // (64, 16)
    ls_kernel<<<grid, 256, SMEM_BYTES>>>(inp, depth, alb, nrm, out);
}

// round 16
// speedup vs baseline: 6.9225x; 1.0282x over previous
#include <cuda_runtime.h>

#define IMW 1024
#define IMH 1024
#define HW  (IMW * IMH)
#define TILE_W 16
#define TILE_H 32
#define HALO_W 22
#define HALO_H 38
#define SSTRIDE 28            // 4*28 % 32 == 16 -> warp halves on disjoint banks
#define CH_STRIDE (HALO_H * SSTRIDE)   // 1064 floats per channel
#define F_WORDS (11 * CH_STRIDE)       // 11704 floats = 46,816 B
#define XSTR 61                         // slot stride (ull), conflict-free
#define X_ULL (128 * XSTR)              // 62,464 B
#define SMEM_BYTES (F_WORDS * 4 + X_ULL * 8)   // 109,280 B -> 2 CTAs/SM
#define EPSR 1e-4f
#define SGN2 0x8000000080000000ULL

typedef unsigned long long ull;

// ---- packed f32x2 helpers -------------------------------------------------
__device__ __forceinline__ ull pk2(float lo, float hi) {
    ull r;
    asm("mov.b64 %0, {%1, %2};" : "=l"(r) : "f"(lo), "f"(hi));
    return r;
}
__device__ __forceinline__ void ffma2(ull& d, ull a, ull b) {
    asm("fma.rn.f32x2 %0, %1, %2, %0;" : "+l"(d) : "l"(a), "l"(b));
}
__device__ __forceinline__ float upk(ull v, int hi) {
    float lo, h;
    asm("mov.b64 {%0, %1}, %2;" : "=f"(lo), "=f"(h) : "l"(v));
    return hi ? h : lo;
}

// one pair-row tap block of 7 horizontal taps; SUB flips sign of 1st operand
template<bool SUB>
__device__ __forceinline__ void tap7(const float* __restrict__ rp,
                                     ull ata[36], ull aty[24]) {
#pragma unroll
    for (int dx = 0; dx < 7; ++dx) {
        ull v[11];
#pragma unroll
        for (int ch = 0; ch < 11; ++ch)
            v[ch] = pk2(rp[ch * CH_STRIDE + dx],
                        rp[ch * CH_STRIDE + dx + SSTRIDE]);
        int k = 0;
#pragma unroll
        for (int i = 0; i < 8; ++i) {
            const ull si = SUB ? (v[i] ^ SGN2) : v[i];
#pragma unroll
            for (int j = i; j < 8; ++j) { ffma2(ata[k], si, v[j]); ++k; }
#pragma unroll
            for (int c = 0; c < 3; ++c) ffma2(aty[i * 3 + c], si, v[8 + c]);
        }
    }
}

// R1's scalar per-pixel solve; consumes ata/aty (their LAST use).
__device__ __forceinline__ void solve2(const ull ata[36], const ull aty[24],
                                       const float* __restrict__ S,
                                       int lp, int lx, int gy, int gx,
                                       float* __restrict__ out) {
#pragma unroll 1
    for (int p = 0; p < 2; ++p) {
        float A[8][9];
        {
            int k = 0;
#pragma unroll
            for (int i = 0; i < 8; ++i)
#pragma unroll
                for (int j = i; j < 8; ++j) {
                    const float vv = upk(ata[k], p); ++k;
                    A[i][j] = vv;
                    A[j][i] = vv;
                }
        }
#pragma unroll
        for (int i = 0; i < 8; ++i) A[i][i] += EPSR;

        const float* cp = &S[(lp + 3 + p) * SSTRIDE + (lx + 3)];
#pragma unroll
        for (int i = 0; i < 8; ++i) A[i][8] = cp[i * CH_STRIDE];

#pragma unroll
        for (int kk = 0; kk < 8; ++kk) {
            const float inv = 1.0f / A[kk][kk];
#pragma unroll
            for (int j = 0; j < 9; ++j)
                if (j > kk) A[kk][j] *= inv;
#pragma unroll
            for (int r = 0; r < 8; ++r)
                if (r > kk) {
                    const float m = A[r][kk];
#pragma unroll
                    for (int j = 0; j < 9; ++j)
                        if (j > kk) A[r][j] = fmaf(-m, A[kk][j], A[r][j]);
                }
        }
        float x[8];
#pragma unroll
        for (int i = 7; i >= 0; --i) {
            float s = A[i][8];
#pragma unroll
            for (int j = 0; j < 8; ++j)
                if (j > i) s = fmaf(-A[i][j], x[j], s);
            x[i] = s;
        }

#pragma unroll
        for (int c = 0; c < 3; ++c) {
            float o = 0.0f;
#pragma unroll
            for (int i = 0; i < 8; ++i)
                o = fmaf(x[i], upk(aty[i * 3 + c], p), o);
            out[c * HW + (gy + p) * IMW + gx] = o;
        }
    }
}

__global__ __launch_bounds__(128)
void ls_kernel(const float* __restrict__ inp,
               const float* __restrict__ depth,
               const float* __restrict__ alb,
               const float* __restrict__ nrm,
               float* __restrict__ out)
{
    extern __shared__ float SM[];
    float* S = SM;                          // S[ch][r][c], stride 28
    ull* X = (ull*)(SM + F_WORDS);          // 128 private slots x 61 ull

    const int tid = threadIdx.x;
    const int bx = blockIdx.x, by = blockIdx.y;
    const int gx0 = bx * TILE_W - 3;
    const int gy0 = by * TILE_H - 3;

    // ---- stage halo tile into smem (zeros outside the image) ----
    for (int idx = tid; idx < HALO_H * HALO_W; idx += 128) {
        const int r = idx / HALO_W;
        const int c = idx - r * HALO_W;
        const int gy = gy0 + r;
        const int gx = gx0 + c;
        float v[11];
        if ((unsigned)gy < (unsigned)IMH && (unsigned)gx < (unsigned)IMW) {
            const int g = gy * IMW + gx;
            v[0] = 1.0f;
            v[1] = depth[g];
            v[2] = alb[g];  v[3] = alb[g + HW];  v[4] = alb[g + 2 * HW];
            v[5] = nrm[g];  v[6] = nrm[g + HW];  v[7] = nrm[g + 2 * HW];
            v[8] = inp[g];  v[9] = inp[g + HW];  v[10] = inp[g + 2 * HW];
        } else {
#pragma unroll
            for (int ch = 0; ch < 11; ++ch) v[ch] = 0.0f;
        }
#pragma unroll
        for (int ch = 0; ch < 11; ++ch)
            S[ch * CH_STRIDE + r * SSTRIDE + c] = v[ch];
    }
    __syncthreads();

    const int lx = tid & 15;
    const int ty = tid >> 4;                // 0..7
    const int lp0 = 4 * ty;                 // pairs at lp0 and lp0+2
    const int gx = bx * TILE_W + lx;
    ull* xp = X + tid * XSTR;

    ull ata[36];
    ull aty[24];
#pragma unroll
    for (int i = 0; i < 36; ++i) ata[i] = 0ULL;
#pragma unroll
    for (int i = 0; i < 24; ++i) aty[i] = 0ULL;

    // ---- pair 0: full 49 taps ----
    {
        const float* base = &S[lp0 * SSTRIDE + lx];
#pragma unroll 1
        for (int dy = 0; dy < 7; ++dy)
            tap7<false>(base + dy * SSTRIDE, ata, aty);
    }

    // ---- stash pair-0 moments (write-only; A still live) ----
#pragma unroll
    for (int m = 0; m < 36; ++m) xp[m] = ata[m];
#pragma unroll
    for (int m = 0; m < 24; ++m) xp[36 + m] = aty[m];

    // ---- solve pair 0: A dies into the solve ----
    solve2(ata, aty, S, lp0, lx, by * TILE_H + lp0, gx, out);

    // ---- lifetime fence: no shared load moves above this barrier ----
    __syncthreads();

    // ---- reload + slide 2 rows -> pair 1 ----
    {
        ull ata2[36];
        ull aty2[24];
#pragma unroll
        for (int m = 0; m < 36; ++m) ata2[m] = xp[m];
#pragma unroll
        for (int m = 0; m < 24; ++m) aty2[m] = xp[36 + m];

        const int lp = lp0 + 2;
        const float* b = &S[lp * SSTRIDE + lx];
        tap7<false>(b + 5 * SSTRIDE, ata2, aty2);
        tap7<false>(b + 6 * SSTRIDE, ata2, aty2);
        tap7<true >(b - 2 * SSTRIDE, ata2, aty2);
        tap7<true >(b - 1 * SSTRIDE, ata2, aty2);

        // solve pair 1: A' dies into the solve
        solve2(ata2, aty2, S, lp, lx, by * TILE_H + lp, gx, out);
    }
}

extern "C" void kernel_launch(void* const* d_in, const int* in_sizes, int n_in,
                              void* d_out, int out_size) {
    const float* inp   = (const float*)d_in[0];
    const float* depth = (const float*)d_in[1];
    const float* alb   = (const float*)d_in[2];
    const float* nrm   = (const float*)d_in[3];
    float* out = (float*)d_out;

    cudaFuncSetAttribute(ls_kernel, cudaFuncAttributeMaxDynamicSharedMemorySize,
                         SMEM_BYTES);
    dim3 grid(IMW / TILE_W, IMH / TILE_H);   // (64, 32) = 2048 CTAs
    ls_kernel<<<grid, 128, SMEM_BYTES>>>(inp, depth, alb, nrm, out);
}